// round 1
// baseline (speedup 1.0000x reference)
#include <cuda_runtime.h>
#include <math.h>

// ---- problem constants ----
#define B_   16
#define L_   128
#define O_   128
#define N_   256
#define S_   64
#define U_   32
#define DEL  64
#define HID  512
#define KC   4
#define CDIM 288           // N_ + U_
#define DOUT 24640         // DEL + N_*U_ + N_*S_
#define TOK  2048          // B_ * L_
#define KDIM 288

// ---- scratch (device globals: no allocation allowed) ----
__device__ float g_p[TOK * N_];        // proj outputs, tokens 0..127 per batch (incl. z0 @127)
__device__ float g_old[TOK * CDIM];    // post-conv silu activations
__device__ float g_gen[TOK * DOUT];    // big GEMM output (~202 MB)
__device__ float g_dA[TOK * N_];
__device__ float g_coeff[TOK * N_];
__device__ float g_Bu[TOK * N_];
__device__ float g_z[TOK * N_];
__device__ float g_part[TOK];          // per-token squared-error partial sums

__device__ __forceinline__ float siluf(float v) { return v / (1.0f + expf(-v)); }

// ------------------------------------------------------------------
// K1: proj_x(v) = relu(v @ W0^T + b0) @ W1^T + b1 for tokens 0..127 of x.
// Block = (batch, 8-token tile); 256 threads.
// ------------------------------------------------------------------
__global__ void __launch_bounds__(256) k_proj(const float* __restrict__ x,
                                              const float* __restrict__ W0,
                                              const float* __restrict__ b0,
                                              const float* __restrict__ W1,
                                              const float* __restrict__ b1) {
    __shared__ float xs[8][64];
    __shared__ float hs[8][512];
    int b  = blockIdx.x >> 4;
    int t0 = (blockIdx.x & 15) * 8;
    int tid = threadIdx.x;

    for (int i = tid; i < 8 * 64; i += 256) {
        int tt = i >> 6, k = i & 63;
        xs[tt][k] = x[(b * (O_ + L_) + t0 + tt) * S_ + k];
    }
    __syncthreads();

    // hidden layer
    #pragma unroll
    for (int jj = 0; jj < 2; jj++) {
        int j = tid + jj * 256;
        float acc[8];
        float bj = b0[j];
        #pragma unroll
        for (int tt = 0; tt < 8; tt++) acc[tt] = bj;
        for (int k = 0; k < 64; k++) {
            float w = W0[j * 64 + k];
            #pragma unroll
            for (int tt = 0; tt < 8; tt++) acc[tt] += w * xs[tt][k];
        }
        #pragma unroll
        for (int tt = 0; tt < 8; tt++) hs[tt][j] = fmaxf(acc[tt], 0.0f);
    }
    __syncthreads();

    // output layer
    int n = tid;
    float acc2[8];
    float bn = b1[n];
    #pragma unroll
    for (int tt = 0; tt < 8; tt++) acc2[tt] = bn;
    for (int j = 0; j < 512; j++) {
        float w = W1[n * 512 + j];
        #pragma unroll
        for (int tt = 0; tt < 8; tt++) acc2[tt] += w * hs[tt][j];
    }
    #pragma unroll
    for (int tt = 0; tt < 8; tt++) g_p[(b * L_ + t0 + tt) * N_ + n] = acc2[tt];
}

// ------------------------------------------------------------------
// K2: silu -> depthwise conv (K=4, pad 3/3, keep last 128 outputs) -> silu.
// old[b,l,c] = silu(cb[c] + sum_k cw[c,k] * silu(seq[b, l+k-1, c])), valid idx 0..126
// seq channel c<256 from proj, c>=256 from u.
// ------------------------------------------------------------------
__global__ void k_conv(const float* __restrict__ u,
                       const float* __restrict__ cw,
                       const float* __restrict__ cb) {
    int tok = blockIdx.x;
    int b = tok >> 7, l = tok & 127;
    int c = threadIdx.x;   // 0..287
    float acc = cb[c];
    #pragma unroll
    for (int k = 0; k < KC; k++) {
        int i = l - 1 + k;
        if (i >= 0 && i <= 126) {
            float v = (c < 256) ? g_p[((b << 7) + i) * N_ + c]
                                : u[(b * 256 + i) * U_ + (c - 256)];
            acc += cw[c * 4 + k] * siluf(v);
        }
    }
    g_old[tok * CDIM + c] = siluf(acc);
}

// ------------------------------------------------------------------
// K3: big SGEMM: g_gen[m][n] = bg[n] + sum_k g_old[m][k] * Wg[n][k]
// M=2048, N=24640, K=288.  BM=BN=128, BK=32, 8x8 microtiles, 256 threads.
// ------------------------------------------------------------------
__global__ void __launch_bounds__(256) k_gemm(const float* __restrict__ Wg,
                                              const float* __restrict__ bg) {
    __shared__ float As[32][132];
    __shared__ float Bs[32][132];
    int m0 = blockIdx.y * 128;
    int n0 = blockIdx.x * 128;
    int tid = threadIdx.x;
    int tx = tid & 15, ty = tid >> 4;

    float acc[8][8];
    #pragma unroll
    for (int i = 0; i < 8; i++)
        #pragma unroll
        for (int j = 0; j < 8; j++) acc[i][j] = 0.0f;

    for (int k0 = 0; k0 < KDIM; k0 += 32) {
        #pragma unroll
        for (int p = 0; p < 4; p++) {
            int f4 = tid + p * 256;
            int row = f4 >> 3, c4 = (f4 & 7) * 4;
            float4 v = *reinterpret_cast<const float4*>(&g_old[(m0 + row) * KDIM + k0 + c4]);
            As[c4 + 0][row] = v.x; As[c4 + 1][row] = v.y;
            As[c4 + 2][row] = v.z; As[c4 + 3][row] = v.w;
        }
        #pragma unroll
        for (int p = 0; p < 4; p++) {
            int f4 = tid + p * 256;
            int row = f4 >> 3, c4 = (f4 & 7) * 4;
            float4 v = make_float4(0.f, 0.f, 0.f, 0.f);
            if (n0 + row < DOUT)
                v = *reinterpret_cast<const float4*>(&Wg[(n0 + row) * KDIM + k0 + c4]);
            Bs[c4 + 0][row] = v.x; Bs[c4 + 1][row] = v.y;
            Bs[c4 + 2][row] = v.z; Bs[c4 + 3][row] = v.w;
        }
        __syncthreads();

        #pragma unroll
        for (int k = 0; k < 32; k++) {
            float a[8], bf[8];
            #pragma unroll
            for (int i = 0; i < 8; i++) a[i]  = As[k][ty * 8 + i];
            #pragma unroll
            for (int j = 0; j < 8; j++) bf[j] = Bs[k][tx * 8 + j];
            #pragma unroll
            for (int i = 0; i < 8; i++)
                #pragma unroll
                for (int j = 0; j < 8; j++) acc[i][j] += a[i] * bf[j];
        }
        __syncthreads();
    }

    #pragma unroll
    for (int j = 0; j < 8; j++) {
        int col = n0 + tx * 8 + j;
        if (col < DOUT) {
            float bb = bg[col];
            #pragma unroll
            for (int i = 0; i < 8; i++)
                g_gen[(size_t)(m0 + ty * 8 + i) * DOUT + col] = acc[i][j] + bb;
        }
    }
}

// ------------------------------------------------------------------
// K4: delta path: delta = softplus(gen[:, :64] @ Wdt^T + bdt);
//     a = -(A>0 ? A : expm1(A)); dA = exp(delta*a); coeff = (dA-1)/a
// ------------------------------------------------------------------
__global__ void k_delta(const float* __restrict__ A,
                        const float* __restrict__ Wdt,
                        const float* __restrict__ bdt) {
    __shared__ float d[64];
    int tok = blockIdx.x;
    int tid = threadIdx.x;
    if (tid < 64) d[tid] = g_gen[(size_t)tok * DOUT + tid];
    __syncthreads();
    int n = tid;
    float acc = bdt[n];
    #pragma unroll 8
    for (int k = 0; k < 64; k++) acc += d[k] * Wdt[n * 64 + k];
    // stable softplus = max(x,0) + log1p(exp(-|x|))
    float sp = fmaxf(acc, 0.0f) + log1pf(expf(-fabsf(acc)));
    float a = A[n];
    float an = (a > 0.0f) ? -a : -expm1f(a);
    float dA = expf(sp * an);
    g_dA[tok * N_ + n] = dA;
    g_coeff[tok * N_ + n] = (dA - 1.0f) / an;
}

// ------------------------------------------------------------------
// K5: Bu[tok][n] = coeff * sum_u Bm[tok][n][u] * u0[tok][u]
//     Bm at gen cols 64 + n*32 + u ; u0 = u[b, 127+t, :]
// ------------------------------------------------------------------
__global__ void k_bu(const float* __restrict__ u) {
    __shared__ float us[32];
    int tok = blockIdx.x;
    int b = tok >> 7, t = tok & 127;
    int tid = threadIdx.x;
    if (tid < 32) us[tid] = u[(b * 256 + 127 + t) * U_ + tid];
    __syncthreads();
    const float* gp = &g_gen[(size_t)tok * DOUT + DEL + tid * U_];
    float acc = 0.0f;
    #pragma unroll
    for (int uu = 0; uu < 32; uu++) acc += gp[uu] * us[uu];
    g_Bu[tok * N_ + tid] = g_coeff[tok * N_ + tid] * acc;
}

// ------------------------------------------------------------------
// K6: sequential scan over t: z = z*dA + Bu, starting from z0 = proj(x[:,127,:])
// ------------------------------------------------------------------
__global__ void k_scan() {
    int b = blockIdx.x;
    int n = threadIdx.x;
    float z = g_p[((b << 7) + 127) * N_ + n];
    for (int t = 0; t < L_; t++) {
        int idx = ((b << 7) + t) * N_ + n;
        z = z * g_dA[idx] + g_Bu[idx];
        g_z[idx] = z;
    }
}

// ------------------------------------------------------------------
// K7: y[b,t,s] = sum_n Cm[tok][n][s] * z[tok][n], Cm at gen col 8256+n*64+s.
//     Writes ys in (t, b, s) order at out[1 + ...]; per-token sq-err partial.
// ------------------------------------------------------------------
__global__ void k_y(const float* __restrict__ x, float* __restrict__ out) {
    __shared__ float zs[256];
    __shared__ float red[2];
    int tok = blockIdx.x;
    int b = tok >> 7, t = tok & 127;
    int s = threadIdx.x;   // 0..63
    for (int i = s; i < 256; i += 64) zs[i] = g_z[tok * N_ + i];
    __syncthreads();
    const float* gp = &g_gen[(size_t)tok * DOUT + DEL + N_ * U_ + s];
    float acc = 0.0f;
    #pragma unroll 8
    for (int n = 0; n < 256; n++) acc += gp[n * 64] * zs[n];
    out[1 + ((t << 4) + b) * S_ + s] = acc;
    float diff = acc - x[(b * 256 + 128 + t) * S_ + s];
    float v = diff * diff;
    #pragma unroll
    for (int o = 16; o > 0; o >>= 1) v += __shfl_down_sync(0xffffffffu, v, o);
    if ((s & 31) == 0) red[s >> 5] = v;
    __syncthreads();
    if (s == 0) g_part[tok] = red[0] + red[1];
}

// ------------------------------------------------------------------
// K8: loss = sum(partials) / (B*S*L)   (mean over (B,S) per step, sum_t / L)
// ------------------------------------------------------------------
__global__ void k_loss(float* __restrict__ out) {
    __shared__ float red[256];
    float v = 0.0f;
    for (int i = threadIdx.x; i < TOK; i += 256) v += g_part[i];
    red[threadIdx.x] = v;
    __syncthreads();
    for (int st = 128; st > 0; st >>= 1) {
        if (threadIdx.x < st) red[threadIdx.x] += red[threadIdx.x + st];
        __syncthreads();
    }
    if (threadIdx.x == 0) out[0] = red[0] / (float)(B_ * S_ * L_);
}

// ------------------------------------------------------------------
extern "C" void kernel_launch(void* const* d_in, const int* in_sizes, int n_in,
                              void* d_out, int out_size) {
    const float* x   = (const float*)d_in[0];
    const float* u   = (const float*)d_in[1];
    const float* A   = (const float*)d_in[2];
    const float* W0  = (const float*)d_in[3];
    const float* b0  = (const float*)d_in[4];
    const float* W1  = (const float*)d_in[5];
    const float* b1  = (const float*)d_in[6];
    const float* cw  = (const float*)d_in[7];
    const float* cb  = (const float*)d_in[8];
    const float* Wg  = (const float*)d_in[9];
    const float* bg  = (const float*)d_in[10];
    const float* Wdt = (const float*)d_in[11];
    const float* bdt = (const float*)d_in[12];
    float* out = (float*)d_out;

    k_proj<<<256, 256>>>(x, W0, b0, W1, b1);
    k_conv<<<TOK, CDIM>>>(u, cw, cb);
    dim3 gg((DOUT + 127) / 128, TOK / 128);   // (193, 16)
    k_gemm<<<gg, 256>>>(Wg, bg);
    k_delta<<<TOK, 256>>>(A, Wdt, bdt);
    k_bu<<<TOK, 256>>>(u);
    k_scan<<<B_, N_>>>();
    k_y<<<TOK, S_>>>(x, out);
    k_loss<<<1, 256>>>(out);
}